// round 7
// baseline (speedup 1.0000x reference)
#include <cuda_runtime.h>

#define NT 384
#define M  8

// ---- shared memory layout (float offsets) ----
#define ENC_W1_ 0        // 20x100
#define ENC_B1_ 2000     // 100
#define ENC_W2_ 2100     // 100x20
#define ENC_B2_ 4100     // 20
#define UB1_    4120     // 200
#define RB1_    4320
#define NB1_    4520
#define UW2_    4720     // 200x40
#define RW2_    12720
#define NW2_    20720
#define UB2_    28720    // 40
#define RB2_    28760
#define NB2_    28800
#define DW1_    28840    // 32x100
#define DB1_    32040    // 100
#define DW2_    32140    // 100x100
#define DB2_    42140    // 100
#define DW3_    42240    // 100x32
#define DB3_    45440    // 32
#define OW_     45472    // 32x128
#define OB_     49568    // 128
#define YC_     49696    // 8x296  [ym(20) ys(20) x(128) ones(128)]
#define HU_     52064    // 8x200
#define HR_     53664    // 8x200
#define YCR_    55264    // 8x40
#define U_      55584    // 8x40
#define R_      55904    // 8x40
#define G_      56224    // 8x40
#define Y0_     56544    // 8x20
#define KACC_   56704    // 8x20
#define YST_    56864    // 8x20
#define KOUT_   57024    // 8x20
#define SMEM_FLOATS 57184
// decoder aliases (encoder buffers no longer live)
#define Z_     U_
#define Y0Z_   R_
#define KACCZ_ G_
#define YSTZ_  YCR_
#define HD1_   HU_
#define HD2_   (HU_ + 800)

struct Params {
    const float* truth; const float* t; const int* obs; const float* eps;
    const float* enc_w1; const float* enc_b1; const float* enc_w2; const float* enc_b2;
    const float* uw1; const float* ub1; const float* uw2; const float* ub2;
    const float* rw1; const float* rb1; const float* rw2; const float* rb2;
    const float* nw1; const float* nb1; const float* nw2; const float* nb2;
    const float* z0w1; const float* z0b1; const float* z0w2; const float* z0b2;
    const float* dw1; const float* db1; const float* dw2; const float* db2;
    const float* dw3; const float* db3;
    const float* ow;  const float* ob;
};

__global__ void __launch_bounds__(NT, 1)
lode_kernel(Params P, float* __restrict__ out)
{
    extern __shared__ float s[];
    const int tid  = threadIdx.x;
    const int row0 = blockIdx.x * M;

    // ---- stage all small weights into SMEM ----
    {
        auto cp = [&](int off, const float* src, int n) {
            for (int i = tid; i < n; i += NT) s[off + i] = src[i];
        };
        cp(ENC_W1_, P.enc_w1, 2000); cp(ENC_B1_, P.enc_b1, 100);
        cp(ENC_W2_, P.enc_w2, 2000); cp(ENC_B2_, P.enc_b2, 20);
        cp(UB1_, P.ub1, 200); cp(RB1_, P.rb1, 200); cp(NB1_, P.nb1, 200);
        cp(UW2_, P.uw2, 8000); cp(RW2_, P.rw2, 8000); cp(NW2_, P.nw2, 8000);
        cp(UB2_, P.ub2, 40);  cp(RB2_, P.rb2, 40);  cp(NB2_, P.nb2, 40);
        cp(DW1_, P.dw1, 3200); cp(DB1_, P.db1, 100);
        cp(DW2_, P.dw2, 10000); cp(DB2_, P.db2, 100);
        cp(DW3_, P.dw3, 3200); cp(DB3_, P.db3, 32);
        cp(OW_,  P.ow, 4096);  cp(OB_,  P.ob, 128);
    }
    // yc init: y=0, x filled per step, ones tail
    for (int i = tid; i < M * 296; i += NT) {
        int k = i % 296;
        s[YC_ + i] = (k >= 168) ? 1.0f : 0.0f;
    }
    __syncthreads();

    const float kw[4] = {1.f, 2.f, 2.f, 1.f};
    const float sa[4] = {0.5f, 0.5f, 1.f, 0.f};

    // ================= ENCODER: 140 reverse-time GRU-ODE steps =================
    for (int st = 0; st < 140; st++) {
        const int oi = P.obs[139 - st];
        float dt = 0.f;
        if (st > 0) dt = P.t[oi] - P.t[P.obs[140 - st]];

        // load x for the 8 rows into yc[40:168]
        for (int i = tid; i < M * 128; i += NT) {
            int j = i >> 7, d = i & 127;
            s[YC_ + j * 296 + 40 + d] =
                P.truth[((size_t)oi * 1024 + row0 + j) * 128 + d];
        }
        if (tid < 160) {
            s[Y0_ + tid]   = s[YC_ + (tid / 20) * 296 + tid % 20];
            s[KACC_ + tid] = 0.f;
        }
        __syncthreads();

        // ---- RK4 on ym with enc MLP (20->100->20) ----
        const float* cur = &s[Y0_];
        for (int e = 0; e < 4; e++) {
            for (int idx = tid; idx < 800; idx += NT) {
                int j = idx / 100, c = idx % 100;
                float acc = s[ENC_B1_ + c];
                const float4* v4 = (const float4*)(cur + j * 20);
                #pragma unroll
                for (int i4 = 0; i4 < 5; i4++) {
                    float4 v = v4[i4]; int i = i4 * 4;
                    acc += v.x * s[ENC_W1_ + (i + 0) * 100 + c]
                         + v.y * s[ENC_W1_ + (i + 1) * 100 + c]
                         + v.z * s[ENC_W1_ + (i + 2) * 100 + c]
                         + v.w * s[ENC_W1_ + (i + 3) * 100 + c];
                }
                s[HU_ + idx] = tanhf(acc);   // layout j*100+c
            }
            __syncthreads();
            if (tid < 160) {
                int j = tid / 20, o = tid % 20;
                float acc = s[ENC_B2_ + o];
                #pragma unroll 4
                for (int c = 0; c < 100; c++)
                    acc += s[HU_ + j * 100 + c] * s[ENC_W2_ + c * 20 + o];
                s[KACC_ + tid] += kw[e] * acc;
                if (e < 3) s[YST_ + tid] = s[Y0_ + tid] + sa[e] * dt * acc;
            }
            __syncthreads();
            cur = &s[YST_];
        }
        if (tid < 160)
            s[YC_ + (tid / 20) * 296 + tid % 20] =
                s[Y0_ + tid] + dt * (1.f / 6.f) * s[KACC_ + tid];
        __syncthreads();

        // ---- gates u,r layer1: 400 cols (200 u + 200 r), 8-row register blocking ----
        for (int cc = tid; cc < 400; cc += NT) {
            const int gate = cc >= 200;
            const int c = gate ? cc - 200 : cc;
            const float* __restrict__ wp = (gate ? P.rw1 : P.uw1) + c;
            float acc[8];
            const float b = s[(gate ? RB1_ : UB1_) + c];
            #pragma unroll
            for (int j = 0; j < 8; j++) acc[j] = b;
            #pragma unroll 2
            for (int k4 = 0; k4 < 74; k4++) {
                const int k = k4 * 4;
                float w0 = wp[(k + 0) * 200], w1v = wp[(k + 1) * 200];
                float w2v = wp[(k + 2) * 200], w3v = wp[(k + 3) * 200];
                #pragma unroll
                for (int j = 0; j < 8; j++) {
                    float4 v = *(const float4*)&s[YC_ + j * 296 + k];
                    acc[j] += v.x * w0 + v.y * w1v + v.z * w2v + v.w * w3v;
                }
            }
            float* ho = gate ? &s[HR_] : &s[HU_];
            #pragma unroll
            for (int j = 0; j < 8; j++) ho[j * 200 + c] = tanhf(acc[j]);
        }
        __syncthreads();

        // ---- gates u,r layer2 + sigmoid: 640 outputs ----
        for (int cc = tid; cc < 640; cc += NT) {
            const int gate = cc >= 320;
            const int idx = gate ? cc - 320 : cc;
            const int j = idx / 40, o = idx % 40;
            const float* h  = gate ? &s[HR_] : &s[HU_];
            const float* w2 = gate ? &s[RW2_] : &s[UW2_];
            float acc = s[(gate ? RB2_ : UB2_) + o];
            #pragma unroll 5
            for (int c4 = 0; c4 < 50; c4++) {
                const int c = c4 * 4;
                float4 hv = *(const float4*)&h[j * 200 + c];
                acc += hv.x * w2[(c + 0) * 40 + o] + hv.y * w2[(c + 1) * 40 + o]
                     + hv.z * w2[(c + 2) * 40 + o] + hv.w * w2[(c + 3) * 40 + o];
            }
            s[(gate ? R_ : U_) + idx] = 1.f / (1.f + expf(-acc));
        }
        __syncthreads();

        if (tid < 320)
            s[YCR_ + tid] = s[YC_ + (tid / 40) * 296 + tid % 40] * s[R_ + tid];
        __syncthreads();

        // ---- n gate layer1: 200 cols x 2 row-groups of 4 ----
        for (int cc = tid; cc < 400; cc += NT) {
            const int c = cc % 200;
            const int jg = cc / 200;
            const float* __restrict__ wp = P.nw1 + c;
            float acc[4];
            const float b = s[NB1_ + c];
            #pragma unroll
            for (int j = 0; j < 4; j++) acc[j] = b;
            #pragma unroll
            for (int k4 = 0; k4 < 10; k4++) {   // k 0..39 from y*r
                const int k = k4 * 4;
                float w0 = wp[(k + 0) * 200], w1v = wp[(k + 1) * 200];
                float w2v = wp[(k + 2) * 200], w3v = wp[(k + 3) * 200];
                #pragma unroll
                for (int j0 = 0; j0 < 4; j0++) {
                    float4 v = *(const float4*)&s[YCR_ + (jg * 4 + j0) * 40 + k];
                    acc[j0] += v.x * w0 + v.y * w1v + v.z * w2v + v.w * w3v;
                }
            }
            #pragma unroll 2
            for (int k4 = 10; k4 < 74; k4++) {  // k 40..295 from [x, ones]
                const int k = k4 * 4;
                float w0 = wp[(k + 0) * 200], w1v = wp[(k + 1) * 200];
                float w2v = wp[(k + 2) * 200], w3v = wp[(k + 3) * 200];
                #pragma unroll
                for (int j0 = 0; j0 < 4; j0++) {
                    float4 v = *(const float4*)&s[YC_ + (jg * 4 + j0) * 296 + k];
                    acc[j0] += v.x * w0 + v.y * w1v + v.z * w2v + v.w * w3v;
                }
            }
            #pragma unroll
            for (int j0 = 0; j0 < 4; j0++)
                s[HU_ + (jg * 4 + j0) * 200 + c] = tanhf(acc[j0]);
        }
        __syncthreads();

        // ---- n gate layer2 + GRU combine ----
        if (tid < 320) {
            const int j = tid / 40, kk = tid % 40;
            float acc = s[NB2_ + kk];
            #pragma unroll 5
            for (int c4 = 0; c4 < 50; c4++) {
                const int c = c4 * 4;
                float4 hv = *(const float4*)&s[HU_ + j * 200 + c];
                acc += hv.x * s[NW2_ + (c + 0) * 40 + kk] + hv.y * s[NW2_ + (c + 1) * 40 + kk]
                     + hv.z * s[NW2_ + (c + 2) * 40 + kk] + hv.w * s[NW2_ + (c + 3) * 40 + kk];
            }
            float nsv = (kk >= 20) ? fabsf(acc) : acc;
            float uu = s[U_ + tid];
            s[YC_ + j * 296 + kk] = (1.f - uu) * nsv + uu * s[YC_ + j * 296 + kk];
        }
        __syncthreads();
    }

    // ================= z0 head + reparameterization =================
    for (int idx = tid; idx < 800; idx += NT) {
        int j = idx / 100, c = idx % 100;
        float acc = P.z0b1[c];
        #pragma unroll
        for (int i4 = 0; i4 < 10; i4++) {
            const int i = i4 * 4;
            float4 v = *(const float4*)&s[YC_ + j * 296 + i];
            acc += v.x * P.z0w1[(i + 0) * 100 + c] + v.y * P.z0w1[(i + 1) * 100 + c]
                 + v.z * P.z0w1[(i + 2) * 100 + c] + v.w * P.z0w1[(i + 3) * 100 + c];
        }
        s[HR_ + idx] = tanhf(acc);   // j*100+c
    }
    __syncthreads();
    for (int idx = tid; idx < 512; idx += NT) {
        int j = idx / 64, o = idx % 64;
        float acc = P.z0b2[o];
        #pragma unroll
        for (int c4 = 0; c4 < 25; c4++) {
            const int c = c4 * 4;
            float4 hv = *(const float4*)&s[HR_ + j * 100 + c];
            acc += hv.x * P.z0w2[(c + 0) * 64 + o] + hv.y * P.z0w2[(c + 1) * 64 + o]
                 + hv.z * P.z0w2[(c + 2) * 64 + o] + hv.w * P.z0w2[(c + 3) * 64 + o];
        }
        s[HU_ + j * 64 + o] = acc;
    }
    __syncthreads();
    if (tid < 256) {
        int j = tid / 32, d = tid % 32;
        float mean = s[HU_ + j * 64 + d];
        float sd   = fabsf(s[HU_ + j * 64 + 32 + d]);
        s[Z_ + tid] = mean + P.eps[(size_t)(row0 + j) * 32 + d] * sd;
    }
    __syncthreads();

    // output projection writer: out[b, tt, :] = z @ out_w + out_b
    auto write_out = [&](int tt) {
        for (int i = tid; i < 1024; i += NT) {
            int j = i >> 7, d = i & 127;
            float acc = s[OB_ + d];
            #pragma unroll
            for (int i4 = 0; i4 < 8; i4++) {
                const int q = i4 * 4;
                float4 v = *(const float4*)&s[Z_ + j * 32 + q];
                acc += v.x * s[OW_ + (q + 0) * 128 + d] + v.y * s[OW_ + (q + 1) * 128 + d]
                     + v.z * s[OW_ + (q + 2) * 128 + d] + v.w * s[OW_ + (q + 3) * 128 + d];
            }
            out[((size_t)(row0 + j) * 200 + tt) * 128 + d] = acc;
        }
    };
    write_out(0);

    // ================= DECODER: 199 RK4 steps of 32->100->100->32 MLP =================
    for (int it = 1; it < 200; it++) {
        const float dt = P.t[it] - P.t[it - 1];
        if (tid < 256) { s[Y0Z_ + tid] = s[Z_ + tid]; s[KACCZ_ + tid] = 0.f; }
        __syncthreads();
        const float* curz = &s[Y0Z_];
        for (int e = 0; e < 4; e++) {
            // L1: 100 cols x 4 row-pairs
            for (int cc = tid; cc < 400; cc += NT) {
                int c = cc % 100, jg = cc / 100;
                float a0 = s[DB1_ + c], a1 = a0;
                #pragma unroll
                for (int i4 = 0; i4 < 8; i4++) {
                    const int i = i4 * 4;
                    float4 v0 = *(const float4*)&curz[(jg * 2 + 0) * 32 + i];
                    float4 v1 = *(const float4*)&curz[(jg * 2 + 1) * 32 + i];
                    float w0 = s[DW1_ + (i + 0) * 100 + c], w1v = s[DW1_ + (i + 1) * 100 + c];
                    float w2v = s[DW1_ + (i + 2) * 100 + c], w3v = s[DW1_ + (i + 3) * 100 + c];
                    a0 += v0.x * w0 + v0.y * w1v + v0.z * w2v + v0.w * w3v;
                    a1 += v1.x * w0 + v1.y * w1v + v1.z * w2v + v1.w * w3v;
                }
                s[HD1_ + (jg * 2 + 0) * 100 + c] = tanhf(a0);
                s[HD1_ + (jg * 2 + 1) * 100 + c] = tanhf(a1);
            }
            __syncthreads();
            // L2: 100x100
            for (int cc = tid; cc < 400; cc += NT) {
                int o = cc % 100, jg = cc / 100;
                float a0 = s[DB2_ + o], a1 = a0;
                #pragma unroll 5
                for (int c4 = 0; c4 < 25; c4++) {
                    const int c = c4 * 4;
                    float4 h0 = *(const float4*)&s[HD1_ + (jg * 2 + 0) * 100 + c];
                    float4 h1 = *(const float4*)&s[HD1_ + (jg * 2 + 1) * 100 + c];
                    float w0 = s[DW2_ + (c + 0) * 100 + o], w1v = s[DW2_ + (c + 1) * 100 + o];
                    float w2v = s[DW2_ + (c + 2) * 100 + o], w3v = s[DW2_ + (c + 3) * 100 + o];
                    a0 += h0.x * w0 + h0.y * w1v + h0.z * w2v + h0.w * w3v;
                    a1 += h1.x * w0 + h1.y * w1v + h1.z * w2v + h1.w * w3v;
                }
                s[HD2_ + (jg * 2 + 0) * 100 + o] = tanhf(a0);
                s[HD2_ + (jg * 2 + 1) * 100 + o] = tanhf(a1);
            }
            __syncthreads();
            // L3 (100->32) fused with RK4 accumulation
            if (tid < 256) {
                int j = tid / 32, o = tid % 32;
                float acc = s[DB3_ + o];
                #pragma unroll 5
                for (int c4 = 0; c4 < 25; c4++) {
                    const int c = c4 * 4;
                    float4 hv = *(const float4*)&s[HD2_ + j * 100 + c];
                    acc += hv.x * s[DW3_ + (c + 0) * 32 + o] + hv.y * s[DW3_ + (c + 1) * 32 + o]
                         + hv.z * s[DW3_ + (c + 2) * 32 + o] + hv.w * s[DW3_ + (c + 3) * 32 + o];
                }
                s[KACCZ_ + tid] += kw[e] * acc;
                if (e < 3) s[YSTZ_ + tid] = s[Y0Z_ + tid] + sa[e] * dt * acc;
            }
            __syncthreads();
            curz = &s[YSTZ_];
        }
        if (tid < 256)
            s[Z_ + tid] = s[Y0Z_ + tid] + dt * (1.f / 6.f) * s[KACCZ_ + tid];
        __syncthreads();
        write_out(it);
    }
}

extern "C" void kernel_launch(void* const* d_in, const int* in_sizes, int n_in,
                              void* d_out, int out_size)
{
    Params P;
    P.truth  = (const float*)d_in[0];  P.t     = (const float*)d_in[1];
    P.obs    = (const int*)  d_in[2];  P.eps   = (const float*)d_in[3];
    P.enc_w1 = (const float*)d_in[4];  P.enc_b1= (const float*)d_in[5];
    P.enc_w2 = (const float*)d_in[6];  P.enc_b2= (const float*)d_in[7];
    P.uw1 = (const float*)d_in[8];  P.ub1 = (const float*)d_in[9];
    P.uw2 = (const float*)d_in[10]; P.ub2 = (const float*)d_in[11];
    P.rw1 = (const float*)d_in[12]; P.rb1 = (const float*)d_in[13];
    P.rw2 = (const float*)d_in[14]; P.rb2 = (const float*)d_in[15];
    P.nw1 = (const float*)d_in[16]; P.nb1 = (const float*)d_in[17];
    P.nw2 = (const float*)d_in[18]; P.nb2 = (const float*)d_in[19];
    P.z0w1= (const float*)d_in[20]; P.z0b1= (const float*)d_in[21];
    P.z0w2= (const float*)d_in[22]; P.z0b2= (const float*)d_in[23];
    P.dw1 = (const float*)d_in[24]; P.db1 = (const float*)d_in[25];
    P.dw2 = (const float*)d_in[26]; P.db2 = (const float*)d_in[27];
    P.dw3 = (const float*)d_in[28]; P.db3 = (const float*)d_in[29];
    P.ow  = (const float*)d_in[30]; P.ob  = (const float*)d_in[31];

    const size_t smem = SMEM_FLOATS * sizeof(float);   // 228,736 B < 227 KB opt-in max
    cudaFuncSetAttribute(lode_kernel,
                         cudaFuncAttributeMaxDynamicSharedMemorySize, (int)smem);
    lode_kernel<<<128, NT, smem>>>(P, (float*)d_out);
}

// round 9
// speedup vs baseline: 1.5833x; 1.5833x over previous
#include <cuda_runtime.h>

#define NT 512
#define M  8

// ---- shared memory layout (float offsets) ----
#define ENC_W1_ 0        // 20x100
#define ENC_B1_ 2000     // 100
#define ENC_W2_ 2100     // 100x20
#define ENC_B2_ 4100     // 20
#define UB1_    4120     // 200 (bias + ones-colsum folded)
#define RB1_    4320
#define NB1_    4520
#define UW2_    4720     // 200x40
#define RW2_    12720
#define NW2_    20720
#define UB2_    28720    // 40
#define RB2_    28760
#define NB2_    28800
#define DW1_    28840    // 32x100
#define DB1_    32040    // 100
#define DW2_    32140    // 100x100
#define DB2_    42140    // 100
#define DW3_    42240    // 100x32
#define DB3_    45440    // 32
#define OW_     45472    // 32x128
#define OB_     49568    // 128
#define T_      49696    // 200
#define OBS_    49896    // 140 (ints)
#define YC_     50036    // 8x168  [ym(20) ys(20) x(128)]  (ones folded into biases)
#define HU_     51380    // 8x200
#define HR_     52980    // 8x200
#define YCR_    54580    // 8x40
#define U_      54900    // 8x40
#define G_      55220    // 8x40
#define Y0_     55540    // 160
#define KACC_   55700    // 160
#define YST_    55860    // 160
#define PART_   56020    // 640
#define SMEM_FLOATS 56660   // 226,640 B

// decoder aliases (encoder buffers dead by then)
#define Z_     U_
#define Y0Z_   YCR_
#define KACCZ_ G_
#define YSTZ_  Y0_
#define HD1_   HU_
#define HD2_   (HU_ + 800)

// transposed gate-w1 weights, k<168 only: [gate][k4][c][4]
__device__ float g_wt[3 * 42 * 200 * 4];

__device__ __forceinline__ float ftanh(float x) {
    float e = __expf(2.f * x);
    return 1.f - __fdividef(2.f, e + 1.f);
}
__device__ __forceinline__ float fsig(float x) {
    return __fdividef(1.f, 1.f + __expf(-x));
}

struct Params {
    const float* truth; const float* t; const int* obs; const float* eps;
    const float* enc_w1; const float* enc_b1; const float* enc_w2; const float* enc_b2;
    const float* uw1; const float* ub1; const float* uw2; const float* ub2;
    const float* rw1; const float* rb1; const float* rw2; const float* rb2;
    const float* nw1; const float* nb1; const float* nw2; const float* nb2;
    const float* z0w1; const float* z0b1; const float* z0w2; const float* z0b2;
    const float* dw1; const float* db1; const float* dw2; const float* db2;
    const float* dw3; const float* db3;
    const float* ow;  const float* ob;
};

__global__ void transpose_w1_kernel(const float* __restrict__ uw1,
                                    const float* __restrict__ rw1,
                                    const float* __restrict__ nw1)
{
    int idx = blockIdx.x * blockDim.x + threadIdx.x;   // over 3*42*200
    if (idx >= 3 * 42 * 200) return;
    int g = idx / (42 * 200);
    int r = idx % (42 * 200);
    int k4 = r / 200, c = r % 200;
    const float* w = (g == 0) ? uw1 : (g == 1) ? rw1 : nw1;
    float4 v;
    v.x = w[(k4 * 4 + 0) * 200 + c];
    v.y = w[(k4 * 4 + 1) * 200 + c];
    v.z = w[(k4 * 4 + 2) * 200 + c];
    v.w = w[(k4 * 4 + 3) * 200 + c];
    ((float4*)g_wt)[idx] = v;
}

__global__ void __launch_bounds__(NT, 1)
lode_kernel(Params P, float* __restrict__ out)
{
    extern __shared__ float s[];
    const int tid  = threadIdx.x;
    const int row0 = blockIdx.x * M;

    // ---- stage all small weights + t/obs into SMEM ----
    {
        auto cp = [&](int off, const float* src, int n) {
            for (int i = tid; i < n; i += NT) s[off + i] = src[i];
        };
        cp(ENC_W1_, P.enc_w1, 2000); cp(ENC_B1_, P.enc_b1, 100);
        cp(ENC_W2_, P.enc_w2, 2000); cp(ENC_B2_, P.enc_b2, 20);
        cp(UB1_, P.ub1, 200); cp(RB1_, P.rb1, 200); cp(NB1_, P.nb1, 200);
        cp(UW2_, P.uw2, 8000); cp(RW2_, P.rw2, 8000); cp(NW2_, P.nw2, 8000);
        cp(UB2_, P.ub2, 40);  cp(RB2_, P.rb2, 40);  cp(NB2_, P.nb2, 40);
        cp(DW1_, P.dw1, 3200); cp(DB1_, P.db1, 100);
        cp(DW2_, P.dw2, 10000); cp(DB2_, P.db2, 100);
        cp(DW3_, P.dw3, 3200); cp(DB3_, P.db3, 32);
        cp(OW_,  P.ow, 4096);  cp(OB_,  P.ob, 128);
        cp(T_,   P.t, 200);
        int* sobs = (int*)&s[OBS_];
        for (int i = tid; i < 140; i += NT) sobs[i] = P.obs[i];
    }
    for (int i = tid; i < M * 168; i += NT) s[YC_ + i] = 0.f;
    __syncthreads();

    // fold ones-column sums (k=168..295) into layer1 biases
    for (int cc = tid; cc < 600; cc += NT) {
        int g = cc / 200, c = cc % 200;
        const float* w = (g == 0) ? P.uw1 : (g == 1) ? P.rw1 : P.nw1;
        float ssum = 0.f;
        #pragma unroll 4
        for (int k = 168; k < 296; k++) ssum += w[k * 200 + c];
        s[((g == 0) ? UB1_ : (g == 1) ? RB1_ : NB1_) + c] += ssum;
    }
    __syncthreads();

    const int* sobs = (const int*)&s[OBS_];
    const float kw[4] = {1.f, 2.f, 2.f, 1.f};
    const float sa[4] = {0.5f, 0.5f, 1.f, 0.f};

    // ================= ENCODER: 140 reverse-time GRU-ODE steps =================
    for (int st = 0; st < 140; st++) {
        const int oi = sobs[139 - st];
        const float dt = (st > 0) ? (s[T_ + oi] - s[T_ + sobs[140 - st]]) : 0.f;

        // load x into yc[40:168]; init Y0/KACC
        for (int i = tid; i < M * 128; i += NT) {
            int j = i >> 7, d = i & 127;
            s[YC_ + j * 168 + 40 + d] =
                P.truth[((size_t)oi * 1024 + row0 + j) * 128 + d];
        }
        if (tid < 160) {
            s[Y0_ + tid]   = s[YC_ + (tid / 20) * 168 + tid % 20];
            s[KACC_ + tid] = 0.f;
        }
        __syncthreads();

        // ---- RK4 on ym: enc MLP 20->100->20 ----
        const float* cur = &s[Y0_];
        for (int e = 0; e < 4; e++) {
            for (int idx = tid; idx < 800; idx += NT) {
                int j = idx / 100, c = idx % 100;
                float a = s[ENC_B1_ + c], b = 0.f;
                const float4* v4 = (const float4*)(cur + j * 20);
                #pragma unroll
                for (int i4 = 0; i4 < 5; i4++) {
                    float4 v = v4[i4]; int i = i4 * 4;
                    a += v.x * s[ENC_W1_ + (i + 0) * 100 + c]
                       + v.y * s[ENC_W1_ + (i + 1) * 100 + c];
                    b += v.z * s[ENC_W1_ + (i + 2) * 100 + c]
                       + v.w * s[ENC_W1_ + (i + 3) * 100 + c];
                }
                s[HU_ + idx] = ftanh(a + b);
            }
            __syncthreads();
            if (tid < 320) {   // split-k2 partials of the 100->20 layer
                int j = tid / 40, rem = tid % 40, p = rem / 20, o = rem % 20;
                int c0 = p ? 52 : 0, nch = p ? 12 : 13;
                float a = p ? 0.f : s[ENC_B2_ + o], b = 0.f;
                for (int c4 = 0; c4 < nch; c4++) {
                    int c = c0 + c4 * 4;
                    float4 hv = *(const float4*)&s[HU_ + j * 100 + c];
                    a += hv.x * s[ENC_W2_ + (c + 0) * 20 + o] + hv.y * s[ENC_W2_ + (c + 1) * 20 + o];
                    b += hv.z * s[ENC_W2_ + (c + 2) * 20 + o] + hv.w * s[ENC_W2_ + (c + 3) * 20 + o];
                }
                s[PART_ + tid] = a + b;
            }
            __syncthreads();
            if (tid < 160) {
                int j = tid / 20, o = tid % 20;
                float a = s[PART_ + j * 40 + o] + s[PART_ + j * 40 + 20 + o];
                if (e < 3) {
                    s[KACC_ + tid] += kw[e] * a;
                    s[YST_ + tid]  = s[Y0_ + tid] + sa[e] * dt * a;
                } else {
                    float ktot = s[KACC_ + tid] + a;
                    s[YC_ + j * 168 + o] = s[Y0_ + tid] + dt * (1.f / 6.f) * ktot;
                }
            }
            __syncthreads();
            cur = &s[YST_];
        }

        // ---- gates u,r layer1 (k<168): 800 items = 2 gates x 200 cols x 2 row-halves
        for (int cc = tid; cc < 800; cc += NT) {
            const int gate = cc >= 400;
            const int t2 = cc - gate * 400;
            const int half = t2 >= 200;
            const int c = t2 - half * 200;
            const float4* __restrict__ wp = (const float4*)g_wt + gate * 8400 + c;
            const float b = s[(gate ? RB1_ : UB1_) + c];
            float a0 = b, a1 = b, a2 = b, a3 = b;
            const int rb = YC_ + (half * 4) * 168;
            #pragma unroll 3
            for (int k4 = 0; k4 < 42; k4++) {
                float4 w = wp[k4 * 200];
                float4 v0 = *(const float4*)&s[rb + 0 * 168 + k4 * 4];
                float4 v1 = *(const float4*)&s[rb + 1 * 168 + k4 * 4];
                float4 v2 = *(const float4*)&s[rb + 2 * 168 + k4 * 4];
                float4 v3 = *(const float4*)&s[rb + 3 * 168 + k4 * 4];
                a0 += v0.x * w.x + v0.y * w.y + v0.z * w.z + v0.w * w.w;
                a1 += v1.x * w.x + v1.y * w.y + v1.z * w.z + v1.w * w.w;
                a2 += v2.x * w.x + v2.y * w.y + v2.z * w.z + v2.w * w.w;
                a3 += v3.x * w.x + v3.y * w.y + v3.z * w.z + v3.w * w.w;
            }
            float* ho = gate ? &s[HR_] : &s[HU_];
            const int ob = (half * 4) * 200 + c;
            ho[ob]       = ftanh(a0);
            ho[ob + 200] = ftanh(a1);
            ho[ob + 400] = ftanh(a2);
            ho[ob + 600] = ftanh(a3);
        }
        __syncthreads();

        // ---- gates u,r layer2: u -> U_, r -> fused into YCR_ = y*r ----
        for (int cc = tid; cc < 640; cc += NT) {
            const int gate = cc >= 320;
            const int idx = cc - gate * 320;
            const int j = idx / 40, o = idx % 40;
            const float* h  = (gate ? &s[HR_] : &s[HU_]) + j * 200;
            const float* w2 = gate ? &s[RW2_] : &s[UW2_];
            float a = s[(gate ? RB2_ : UB2_) + o], b = 0.f;
            #pragma unroll 5
            for (int c4 = 0; c4 < 50; c4++) {
                const int c = c4 * 4;
                float4 hv = *(const float4*)&h[c];
                a += hv.x * w2[(c + 0) * 40 + o] + hv.y * w2[(c + 1) * 40 + o];
                b += hv.z * w2[(c + 2) * 40 + o] + hv.w * w2[(c + 3) * 40 + o];
            }
            float sg = fsig(a + b);
            if (gate) s[YCR_ + idx] = sg * s[YC_ + j * 168 + o];
            else      s[U_ + idx]   = sg;
        }
        __syncthreads();

        // ---- n gate layer1 (k<168): 800 items = 200 cols x 4 row-pairs ----
        for (int cc = tid; cc < 800; cc += NT) {
            const int c = cc % 200, pr = cc / 200;
            const int r0 = pr * 2;
            const float4* __restrict__ wp = (const float4*)g_wt + 2 * 8400 + c;
            const float b = s[NB1_ + c];
            float a0 = b, a1 = b;
            #pragma unroll
            for (int k4 = 0; k4 < 10; k4++) {      // y*r part
                float4 w = wp[k4 * 200];
                float4 v0 = *(const float4*)&s[YCR_ + r0 * 40 + k4 * 4];
                float4 v1 = *(const float4*)&s[YCR_ + (r0 + 1) * 40 + k4 * 4];
                a0 += v0.x * w.x + v0.y * w.y + v0.z * w.z + v0.w * w.w;
                a1 += v1.x * w.x + v1.y * w.y + v1.z * w.z + v1.w * w.w;
            }
            #pragma unroll 4
            for (int k4 = 10; k4 < 42; k4++) {     // x part
                float4 w = wp[k4 * 200];
                float4 v0 = *(const float4*)&s[YC_ + r0 * 168 + k4 * 4];
                float4 v1 = *(const float4*)&s[YC_ + (r0 + 1) * 168 + k4 * 4];
                a0 += v0.x * w.x + v0.y * w.y + v0.z * w.z + v0.w * w.w;
                a1 += v1.x * w.x + v1.y * w.y + v1.z * w.z + v1.w * w.w;
            }
            s[HU_ + r0 * 200 + c]       = ftanh(a0);
            s[HU_ + (r0 + 1) * 200 + c] = ftanh(a1);
        }
        __syncthreads();

        // ---- n layer2 split-k2 partials ----
        for (int ii = tid; ii < 640; ii += NT) {
            const int p = ii / 320, rem = ii % 320;
            const int j = rem / 40, kk = rem % 40;
            const int c0 = p * 100;
            float a = p ? 0.f : s[NB2_ + kk], b = 0.f;
            #pragma unroll 5
            for (int c4 = 0; c4 < 25; c4++) {
                const int c = c0 + c4 * 4;
                float4 hv = *(const float4*)&s[HU_ + j * 200 + c];
                a += hv.x * s[NW2_ + (c + 0) * 40 + kk] + hv.y * s[NW2_ + (c + 1) * 40 + kk];
                b += hv.z * s[NW2_ + (c + 2) * 40 + kk] + hv.w * s[NW2_ + (c + 3) * 40 + kk];
            }
            s[PART_ + ii] = a + b;
        }
        __syncthreads();

        // ---- GRU combine ----
        if (tid < 320) {
            float a = s[PART_ + tid] + s[PART_ + 320 + tid];
            const int j = tid / 40, kk = tid % 40;
            float ns = (kk >= 20) ? fabsf(a) : a;
            float u = s[U_ + tid];
            s[YC_ + j * 168 + kk] = (1.f - u) * ns + u * s[YC_ + j * 168 + kk];
        }
        __syncthreads();
    }

    // ================= z0 head + reparameterization =================
    for (int idx = tid; idx < 800; idx += NT) {
        int j = idx / 100, c = idx % 100;
        float a = P.z0b1[c], b = 0.f;
        #pragma unroll
        for (int i4 = 0; i4 < 10; i4++) {
            const int i = i4 * 4;
            float4 v = *(const float4*)&s[YC_ + j * 168 + i];
            a += v.x * P.z0w1[(i + 0) * 100 + c] + v.y * P.z0w1[(i + 1) * 100 + c];
            b += v.z * P.z0w1[(i + 2) * 100 + c] + v.w * P.z0w1[(i + 3) * 100 + c];
        }
        s[HR_ + idx] = ftanh(a + b);
    }
    __syncthreads();
    {
        int idx = tid;   // exactly 512 items
        int j = idx / 64, o = idx % 64;
        float a = P.z0b2[o], b = 0.f;
        #pragma unroll
        for (int c4 = 0; c4 < 25; c4++) {
            const int c = c4 * 4;
            float4 hv = *(const float4*)&s[HR_ + j * 100 + c];
            a += hv.x * P.z0w2[(c + 0) * 64 + o] + hv.y * P.z0w2[(c + 1) * 64 + o];
            b += hv.z * P.z0w2[(c + 2) * 64 + o] + hv.w * P.z0w2[(c + 3) * 64 + o];
        }
        s[HU_ + idx] = a + b;
    }
    __syncthreads();
    if (tid < 256) {
        int j = tid / 32, d = tid % 32;
        float mean = s[HU_ + j * 64 + d];
        float sd   = fabsf(s[HU_ + j * 64 + 32 + d]);
        float z = mean + P.eps[(size_t)(row0 + j) * 32 + d] * sd;
        s[Z_ + tid]     = z;
        s[Y0Z_ + tid]   = z;
        s[KACCZ_ + tid] = 0.f;
    }
    __syncthreads();

    // output projection writer
    auto write_out = [&](int tt) {
        for (int i = tid; i < 1024; i += NT) {
            int j = i >> 7, d = i & 127;
            float a = s[OB_ + d], b = 0.f;
            #pragma unroll
            for (int i4 = 0; i4 < 8; i4++) {
                const int q = i4 * 4;
                float4 v = *(const float4*)&s[Z_ + j * 32 + q];
                a += v.x * s[OW_ + (q + 0) * 128 + d] + v.y * s[OW_ + (q + 1) * 128 + d];
                b += v.z * s[OW_ + (q + 2) * 128 + d] + v.w * s[OW_ + (q + 3) * 128 + d];
            }
            out[((size_t)(row0 + j) * 200 + tt) * 128 + d] = a + b;
        }
    };
    write_out(0);

    // ================= DECODER: 199 RK4 steps, MLP 32->100->100->32 =================
    for (int it = 1; it < 200; it++) {
        const float dt = s[T_ + it] - s[T_ + it - 1];
        const float* curz = &s[Y0Z_];
        for (int e = 0; e < 4; e++) {
            // L1: 100 cols x 4 row-pairs
            for (int cc = tid; cc < 400; cc += NT) {
                const int c = cc % 100, jg = cc / 100, r0 = jg * 2;
                const float b0 = s[DB1_ + c];
                float a0 = b0, a1 = b0;
                #pragma unroll
                for (int i4 = 0; i4 < 8; i4++) {
                    const int i = i4 * 4;
                    float4 v0 = *(const float4*)&curz[r0 * 32 + i];
                    float4 v1 = *(const float4*)&curz[(r0 + 1) * 32 + i];
                    float w0 = s[DW1_ + (i + 0) * 100 + c], w1v = s[DW1_ + (i + 1) * 100 + c];
                    float w2v = s[DW1_ + (i + 2) * 100 + c], w3v = s[DW1_ + (i + 3) * 100 + c];
                    a0 += v0.x * w0 + v0.y * w1v + v0.z * w2v + v0.w * w3v;
                    a1 += v1.x * w0 + v1.y * w1v + v1.z * w2v + v1.w * w3v;
                }
                s[HD1_ + r0 * 100 + c]       = ftanh(a0);
                s[HD1_ + (r0 + 1) * 100 + c] = ftanh(a1);
            }
            __syncthreads();
            // L2: 100x100
            for (int cc = tid; cc < 400; cc += NT) {
                const int o = cc % 100, jg = cc / 100, r0 = jg * 2;
                const float b0 = s[DB2_ + o];
                float a0 = b0, a1 = b0, a2 = 0.f, a3 = 0.f;
                #pragma unroll 5
                for (int c4 = 0; c4 < 25; c4++) {
                    const int c = c4 * 4;
                    float4 h0 = *(const float4*)&s[HD1_ + r0 * 100 + c];
                    float4 h1 = *(const float4*)&s[HD1_ + (r0 + 1) * 100 + c];
                    float w0 = s[DW2_ + (c + 0) * 100 + o], w1v = s[DW2_ + (c + 1) * 100 + o];
                    float w2v = s[DW2_ + (c + 2) * 100 + o], w3v = s[DW2_ + (c + 3) * 100 + o];
                    a0 += h0.x * w0 + h0.y * w1v;  a2 += h0.z * w2v + h0.w * w3v;
                    a1 += h1.x * w0 + h1.y * w1v;  a3 += h1.z * w2v + h1.w * w3v;
                }
                s[HD2_ + r0 * 100 + o]       = ftanh(a0 + a2);
                s[HD2_ + (r0 + 1) * 100 + o] = ftanh(a1 + a3);
            }
            __syncthreads();
            // L3 (100->32) split-k2 partials: exactly 512 items
            {
                const int ii = tid;
                const int p = ii / 256, rem = ii % 256;
                const int j = rem / 32, o = rem % 32;
                const int c0 = p ? 52 : 0, nch = p ? 12 : 13;
                float a = p ? 0.f : s[DB3_ + o], b = 0.f;
                for (int c4 = 0; c4 < nch; c4++) {
                    const int c = c0 + c4 * 4;
                    float4 hv = *(const float4*)&s[HD2_ + j * 100 + c];
                    a += hv.x * s[DW3_ + (c + 0) * 32 + o] + hv.y * s[DW3_ + (c + 1) * 32 + o];
                    b += hv.z * s[DW3_ + (c + 2) * 32 + o] + hv.w * s[DW3_ + (c + 3) * 32 + o];
                }
                s[PART_ + ii] = a + b;
            }
            __syncthreads();
            if (tid < 256) {
                float a = s[PART_ + tid] + s[PART_ + 256 + tid];
                if (e < 3) {
                    s[KACCZ_ + tid] += kw[e] * a;
                    s[YSTZ_ + tid]   = s[Y0Z_ + tid] + sa[e] * dt * a;
                } else {
                    float ktot = s[KACCZ_ + tid] + a;
                    float z = s[Y0Z_ + tid] + dt * (1.f / 6.f) * ktot;
                    s[Z_ + tid]     = z;
                    s[Y0Z_ + tid]   = z;
                    s[KACCZ_ + tid] = 0.f;
                }
            }
            __syncthreads();
            curz = &s[YSTZ_];
        }
        write_out(it);
    }
}

extern "C" void kernel_launch(void* const* d_in, const int* in_sizes, int n_in,
                              void* d_out, int out_size)
{
    Params P;
    P.truth  = (const float*)d_in[0];  P.t     = (const float*)d_in[1];
    P.obs    = (const int*)  d_in[2];  P.eps   = (const float*)d_in[3];
    P.enc_w1 = (const float*)d_in[4];  P.enc_b1= (const float*)d_in[5];
    P.enc_w2 = (const float*)d_in[6];  P.enc_b2= (const float*)d_in[7];
    P.uw1 = (const float*)d_in[8];  P.ub1 = (const float*)d_in[9];
    P.uw2 = (const float*)d_in[10]; P.ub2 = (const float*)d_in[11];
    P.rw1 = (const float*)d_in[12]; P.rb1 = (const float*)d_in[13];
    P.rw2 = (const float*)d_in[14]; P.rb2 = (const float*)d_in[15];
    P.nw1 = (const float*)d_in[16]; P.nb1 = (const float*)d_in[17];
    P.nw2 = (const float*)d_in[18]; P.nb2 = (const float*)d_in[19];
    P.z0w1= (const float*)d_in[20]; P.z0b1= (const float*)d_in[21];
    P.z0w2= (const float*)d_in[22]; P.z0b2= (const float*)d_in[23];
    P.dw1 = (const float*)d_in[24]; P.db1 = (const float*)d_in[25];
    P.dw2 = (const float*)d_in[26]; P.db2 = (const float*)d_in[27];
    P.dw3 = (const float*)d_in[28]; P.db3 = (const float*)d_in[29];
    P.ow  = (const float*)d_in[30]; P.ob  = (const float*)d_in[31];

    transpose_w1_kernel<<<(3 * 42 * 200 + 255) / 256, 256>>>(P.uw1, P.rw1, P.nw1);

    const size_t smem = SMEM_FLOATS * sizeof(float);   // 226,640 B
    cudaFuncSetAttribute(lode_kernel,
                         cudaFuncAttributeMaxDynamicSharedMemorySize, (int)smem);
    lode_kernel<<<128, NT, smem>>>(P, (float*)d_out);
}

// round 10
// speedup vs baseline: 1.8280x; 1.1546x over previous
#include <cuda_runtime.h>

#define NT 256
#define M  4

// ---- shared memory layout (float offsets) ----
// W region: encoder = UW2(8000)+RW2(8000); decoder aliases DW1/DB1/DW2/DB2/DW3/DB3
#define UW2_    0
#define RW2_    8000
#define WREG_END 16640
// decoder aliases inside W region
#define DW1_    0        // 3200
#define DB1_    3200     // 100
#define DW2_    3300     // 10000
#define DB2_    13300    // 100
#define DW3_    13400    // 3200
#define DB3_    16600    // 32
// persistent
#define ENCW2s_ 16640    // 2000
#define ENCB1s_ 18640    // 100
#define ENCB2s_ 18740    // 20
#define UB1_    18760    // 200 (bias + ones-colsum folded)
#define RB1_    18960
#define NB1_    19160
#define UB2_    19360    // 40
#define RB2_    19400
#define NB2_    19440
#define T_      19480    // 200
#define OBS_    19680    // 140 ints
#define YC_     19820    // 4x168 [ym(20) ys(20) x(128)]
#define HU_     20492    // 4x200
#define HR_     21292    // 4x200
#define YCR_    22092    // 4x40
#define U_      22252    // 4x40
#define Y0_     22412    // 80
#define KACC_   22492    // 80
#define YST_    22572    // 80
#define SMEM_FLOATS 22652   // 90,608 B  -> 2 blocks/SM
// decoder activation aliases
#define HD1_    HU_          // 400
#define HD2_    (HU_ + 400)  // 400
#define Y0Z_    HR_          // 128
#define KACCZ_  (HR_ + 128)  // 128
#define YSTZ_   (HR_ + 256)  // 128

// transposed gate-w1 weights, k<168 only: [gate][k4][c][4]
__device__ float g_wt[3 * 42 * 200 * 4];
// z trajectory scratch: [t][b][32]
__device__ float g_zs[(size_t)200 * 1024 * 32];

__device__ __forceinline__ float ftanh(float x) {
    float e = __expf(2.f * x);
    return 1.f - __fdividef(2.f, e + 1.f);
}
__device__ __forceinline__ float fsig(float x) {
    return __fdividef(1.f, 1.f + __expf(-x));
}

struct Params {
    const float* truth; const float* t; const int* obs; const float* eps;
    const float* enc_w1; const float* enc_b1; const float* enc_w2; const float* enc_b2;
    const float* uw1; const float* ub1; const float* uw2; const float* ub2;
    const float* rw1; const float* rb1; const float* rw2; const float* rb2;
    const float* nw1; const float* nb1; const float* nw2; const float* nb2;
    const float* z0w1; const float* z0b1; const float* z0w2; const float* z0b2;
    const float* dw1; const float* db1; const float* dw2; const float* db2;
    const float* dw3; const float* db3;
    const float* ow;  const float* ob;
};

__global__ void transpose_w1_kernel(const float* __restrict__ uw1,
                                    const float* __restrict__ rw1,
                                    const float* __restrict__ nw1)
{
    int idx = blockIdx.x * blockDim.x + threadIdx.x;
    if (idx >= 3 * 42 * 200) return;
    int g = idx / (42 * 200);
    int r = idx % (42 * 200);
    int k4 = r / 200, c = r % 200;
    const float* w = (g == 0) ? uw1 : (g == 1) ? rw1 : nw1;
    float4 v;
    v.x = w[(k4 * 4 + 0) * 200 + c];
    v.y = w[(k4 * 4 + 1) * 200 + c];
    v.z = w[(k4 * 4 + 2) * 200 + c];
    v.w = w[(k4 * 4 + 3) * 200 + c];
    ((float4*)g_wt)[idx] = v;
}

__global__ void __launch_bounds__(NT, 2)
lode_kernel(Params P, float* __restrict__ out)
{
    extern __shared__ float s[];
    const int tid  = threadIdx.x;
    const int row0 = blockIdx.x * M;

    // ---- stage persistent weights/biases ----
    {
        auto cp = [&](int off, const float* src, int n) {
            for (int i = tid; i < n; i += NT) s[off + i] = src[i];
        };
        cp(UW2_, P.uw2, 8000); cp(RW2_, P.rw2, 8000);
        cp(ENCW2s_, P.enc_w2, 2000);
        cp(ENCB1s_, P.enc_b1, 100); cp(ENCB2s_, P.enc_b2, 20);
        cp(UB1_, P.ub1, 200); cp(RB1_, P.rb1, 200); cp(NB1_, P.nb1, 200);
        cp(UB2_, P.ub2, 40);  cp(RB2_, P.rb2, 40);  cp(NB2_, P.nb2, 40);
        cp(T_,   P.t, 200);
        int* sobs = (int*)&s[OBS_];
        for (int i = tid; i < 140; i += NT) sobs[i] = P.obs[i];
    }
    for (int i = tid; i < M * 168; i += NT) s[YC_ + i] = 0.f;
    __syncthreads();

    // fold ones-column sums (k=168..295) into layer1 biases
    for (int cc = tid; cc < 600; cc += NT) {
        int g = cc / 200, c = cc % 200;
        const float* w = (g == 0) ? P.uw1 : (g == 1) ? P.rw1 : P.nw1;
        float ssum = 0.f;
        #pragma unroll 4
        for (int k = 168; k < 296; k++) ssum += w[k * 200 + c];
        s[((g == 0) ? UB1_ : (g == 1) ? RB1_ : NB1_) + c] += ssum;
    }
    __syncthreads();

    const int* sobs = (const int*)&s[OBS_];
    const float kw[4] = {1.f, 2.f, 2.f, 1.f};
    const float sa[4] = {0.5f, 0.5f, 1.f, 0.f};

    // ================= ENCODER: 140 reverse-time GRU-ODE steps =================
    for (int st = 0; st < 140; st++) {
        const int oi = sobs[139 - st];
        const float dt = (st > 0) ? (s[T_ + oi] - s[T_ + sobs[140 - st]]) : 0.f;

        for (int i = tid; i < M * 128; i += NT) {
            int j = i >> 7, d = i & 127;
            s[YC_ + j * 168 + 40 + d] =
                P.truth[((size_t)oi * 1024 + row0 + j) * 128 + d];
        }
        if (tid < 80) {
            s[Y0_ + tid]   = s[YC_ + (tid / 20) * 168 + tid % 20];
            s[KACC_ + tid] = 0.f;
        }
        __syncthreads();

        // ---- RK4 on ym: enc MLP 20->100->20 ----
        const float* cur = &s[Y0_];
        for (int e = 0; e < 4; e++) {
            if (tid < 200) {   // L1: 100 cols x 2 row-pairs (enc_w1 streamed)
                const int c = tid % 100, r0 = (tid / 100) * 2;
                const float bb = s[ENCB1s_ + c];
                float a0 = bb, b0 = 0.f, a1 = bb, b1 = 0.f;
                #pragma unroll
                for (int i4 = 0; i4 < 5; i4++) {
                    const int i = i4 * 4;
                    float4 v0 = *(const float4*)&cur[r0 * 20 + i];
                    float4 v1 = *(const float4*)&cur[(r0 + 1) * 20 + i];
                    float w0 = __ldg(P.enc_w1 + (i + 0) * 100 + c);
                    float w1v = __ldg(P.enc_w1 + (i + 1) * 100 + c);
                    float w2v = __ldg(P.enc_w1 + (i + 2) * 100 + c);
                    float w3v = __ldg(P.enc_w1 + (i + 3) * 100 + c);
                    a0 += v0.x * w0 + v0.y * w1v;  b0 += v0.z * w2v + v0.w * w3v;
                    a1 += v1.x * w0 + v1.y * w1v;  b1 += v1.z * w2v + v1.w * w3v;
                }
                s[HU_ + r0 * 100 + c]       = ftanh(a0 + b0);
                s[HU_ + (r0 + 1) * 100 + c] = ftanh(a1 + b1);
            }
            __syncthreads();
            if (tid < 80) {    // L2 (100->20) full dot + RK4 update
                const int j = tid / 20, o = tid % 20;
                float a = s[ENCB2s_ + o], b = 0.f;
                #pragma unroll 5
                for (int c4 = 0; c4 < 25; c4++) {
                    const int c = c4 * 4;
                    float4 hv = *(const float4*)&s[HU_ + j * 100 + c];
                    a += hv.x * s[ENCW2s_ + (c + 0) * 20 + o] + hv.y * s[ENCW2s_ + (c + 1) * 20 + o];
                    b += hv.z * s[ENCW2s_ + (c + 2) * 20 + o] + hv.w * s[ENCW2s_ + (c + 3) * 20 + o];
                }
                float acc = a + b;
                if (e < 3) {
                    s[KACC_ + tid] += kw[e] * acc;
                    s[YST_ + tid]   = s[Y0_ + tid] + sa[e] * dt * acc;
                } else {
                    s[YC_ + j * 168 + o] =
                        s[Y0_ + tid] + dt * (1.f / 6.f) * (s[KACC_ + tid] + acc);
                }
            }
            __syncthreads();
            cur = &s[YST_];
        }

        // ---- gates u,r layer1 (k<168): 400 items = 2 gates x 200 cols, 4 rows each
        for (int cc = tid; cc < 400; cc += NT) {
            const int gate = cc >= 200;
            const int c = cc - gate * 200;
            const float4* __restrict__ wp = (const float4*)g_wt + gate * 8400 + c;
            const float b = s[(gate ? RB1_ : UB1_) + c];
            float a0 = b, a1 = b, a2 = b, a3 = b;
            #pragma unroll 3
            for (int k4 = 0; k4 < 42; k4++) {
                float4 w = wp[k4 * 200];
                float4 v0 = *(const float4*)&s[YC_ + 0 * 168 + k4 * 4];
                float4 v1 = *(const float4*)&s[YC_ + 1 * 168 + k4 * 4];
                float4 v2 = *(const float4*)&s[YC_ + 2 * 168 + k4 * 4];
                float4 v3 = *(const float4*)&s[YC_ + 3 * 168 + k4 * 4];
                a0 += v0.x * w.x + v0.y * w.y + v0.z * w.z + v0.w * w.w;
                a1 += v1.x * w.x + v1.y * w.y + v1.z * w.z + v1.w * w.w;
                a2 += v2.x * w.x + v2.y * w.y + v2.z * w.z + v2.w * w.w;
                a3 += v3.x * w.x + v3.y * w.y + v3.z * w.z + v3.w * w.w;
            }
            float* ho = gate ? &s[HR_] : &s[HU_];
            ho[0 * 200 + c] = ftanh(a0);
            ho[1 * 200 + c] = ftanh(a1);
            ho[2 * 200 + c] = ftanh(a2);
            ho[3 * 200 + c] = ftanh(a3);
        }
        __syncthreads();

        // ---- gates u,r layer2: 160 items (gate x rowpair x 40), SMEM weights ----
        if (tid < 160) {
            const int gate = tid >= 80;
            const int idx = tid - gate * 80;
            const int o = idx % 40, r0 = (idx / 40) * 2;
            const float* h  = gate ? &s[HR_] : &s[HU_];
            const float* w2 = gate ? &s[RW2_] : &s[UW2_];
            const float bb = s[(gate ? RB2_ : UB2_) + o];
            float a0 = bb, b0 = 0.f, a1 = bb, b1 = 0.f;
            #pragma unroll 5
            for (int c4 = 0; c4 < 50; c4++) {
                const int c = c4 * 4;
                float4 h0 = *(const float4*)&h[r0 * 200 + c];
                float4 h1 = *(const float4*)&h[(r0 + 1) * 200 + c];
                float w0 = w2[(c + 0) * 40 + o], w1v = w2[(c + 1) * 40 + o];
                float w2v = w2[(c + 2) * 40 + o], w3v = w2[(c + 3) * 40 + o];
                a0 += h0.x * w0 + h0.y * w1v;  b0 += h0.z * w2v + h0.w * w3v;
                a1 += h1.x * w0 + h1.y * w1v;  b1 += h1.z * w2v + h1.w * w3v;
            }
            float sg0 = fsig(a0 + b0), sg1 = fsig(a1 + b1);
            if (gate) {
                s[YCR_ + r0 * 40 + o]       = sg0 * s[YC_ + r0 * 168 + o];
                s[YCR_ + (r0 + 1) * 40 + o] = sg1 * s[YC_ + (r0 + 1) * 168 + o];
            } else {
                s[U_ + r0 * 40 + o]       = sg0;
                s[U_ + (r0 + 1) * 40 + o] = sg1;
            }
        }
        __syncthreads();

        // ---- n gate layer1 (k<168): 200 items (cols), 4 rows each ----
        if (tid < 200) {
            const int c = tid;
            const float4* __restrict__ wp = (const float4*)g_wt + 2 * 8400 + c;
            const float b = s[NB1_ + c];
            float a0 = b, a1 = b, a2 = b, a3 = b;
            #pragma unroll
            for (int k4 = 0; k4 < 10; k4++) {      // y*r part
                float4 w = wp[k4 * 200];
                float4 v0 = *(const float4*)&s[YCR_ + 0 * 40 + k4 * 4];
                float4 v1 = *(const float4*)&s[YCR_ + 1 * 40 + k4 * 4];
                float4 v2 = *(const float4*)&s[YCR_ + 2 * 40 + k4 * 4];
                float4 v3 = *(const float4*)&s[YCR_ + 3 * 40 + k4 * 4];
                a0 += v0.x * w.x + v0.y * w.y + v0.z * w.z + v0.w * w.w;
                a1 += v1.x * w.x + v1.y * w.y + v1.z * w.z + v1.w * w.w;
                a2 += v2.x * w.x + v2.y * w.y + v2.z * w.z + v2.w * w.w;
                a3 += v3.x * w.x + v3.y * w.y + v3.z * w.z + v3.w * w.w;
            }
            #pragma unroll 4
            for (int k4 = 10; k4 < 42; k4++) {     // x part
                float4 w = wp[k4 * 200];
                float4 v0 = *(const float4*)&s[YC_ + 0 * 168 + k4 * 4];
                float4 v1 = *(const float4*)&s[YC_ + 1 * 168 + k4 * 4];
                float4 v2 = *(const float4*)&s[YC_ + 2 * 168 + k4 * 4];
                float4 v3 = *(const float4*)&s[YC_ + 3 * 168 + k4 * 4];
                a0 += v0.x * w.x + v0.y * w.y + v0.z * w.z + v0.w * w.w;
                a1 += v1.x * w.x + v1.y * w.y + v1.z * w.z + v1.w * w.w;
                a2 += v2.x * w.x + v2.y * w.y + v2.z * w.z + v2.w * w.w;
                a3 += v3.x * w.x + v3.y * w.y + v3.z * w.z + v3.w * w.w;
            }
            s[HU_ + 0 * 200 + c] = ftanh(a0);
            s[HU_ + 1 * 200 + c] = ftanh(a1);
            s[HU_ + 2 * 200 + c] = ftanh(a2);
            s[HU_ + 3 * 200 + c] = ftanh(a3);
        }
        __syncthreads();

        // ---- n layer2 (NW2 streamed) + GRU combine fused ----
        if (tid < 160) {
            const int j = tid / 40, kk = tid % 40;
            const float* __restrict__ nw2 = P.nw2;
            float a = s[NB2_ + kk], b = 0.f;
            #pragma unroll 5
            for (int c4 = 0; c4 < 50; c4++) {
                const int c = c4 * 4;
                float4 hv = *(const float4*)&s[HU_ + j * 200 + c];
                a += hv.x * __ldg(nw2 + (c + 0) * 40 + kk) + hv.y * __ldg(nw2 + (c + 1) * 40 + kk);
                b += hv.z * __ldg(nw2 + (c + 2) * 40 + kk) + hv.w * __ldg(nw2 + (c + 3) * 40 + kk);
            }
            float acc = a + b;
            float ns = (kk >= 20) ? fabsf(acc) : acc;
            float u = s[U_ + tid];
            s[YC_ + j * 168 + kk] = (1.f - u) * ns + u * s[YC_ + j * 168 + kk];
        }
        __syncthreads();
    }

    // ================= z0 head + reparameterization =================
    if (tid < 200) {   // L1: 40->100, 2 row-pairs (z0w1 streamed)
        const int c = tid % 100, r0 = (tid / 100) * 2;
        const float bb = __ldg(P.z0b1 + c);
        float a0 = bb, b0 = 0.f, a1 = bb, b1 = 0.f;
        #pragma unroll
        for (int i4 = 0; i4 < 10; i4++) {
            const int i = i4 * 4;
            float4 v0 = *(const float4*)&s[YC_ + r0 * 168 + i];
            float4 v1 = *(const float4*)&s[YC_ + (r0 + 1) * 168 + i];
            float w0 = __ldg(P.z0w1 + (i + 0) * 100 + c);
            float w1v = __ldg(P.z0w1 + (i + 1) * 100 + c);
            float w2v = __ldg(P.z0w1 + (i + 2) * 100 + c);
            float w3v = __ldg(P.z0w1 + (i + 3) * 100 + c);
            a0 += v0.x * w0 + v0.y * w1v;  b0 += v0.z * w2v + v0.w * w3v;
            a1 += v1.x * w0 + v1.y * w1v;  b1 += v1.z * w2v + v1.w * w3v;
        }
        s[HR_ + r0 * 100 + c]       = ftanh(a0 + b0);
        s[HR_ + (r0 + 1) * 100 + c] = ftanh(a1 + b1);
    }
    __syncthreads();
    {   // L2: 100->64, 256 items (z0w2 streamed); write to HU
        const int j = tid / 64, o = tid % 64;
        float a = __ldg(P.z0b2 + o), b = 0.f;
        #pragma unroll 5
        for (int c4 = 0; c4 < 25; c4++) {
            const int c = c4 * 4;
            float4 hv = *(const float4*)&s[HR_ + j * 100 + c];
            a += hv.x * __ldg(P.z0w2 + (c + 0) * 64 + o) + hv.y * __ldg(P.z0w2 + (c + 1) * 64 + o);
            b += hv.z * __ldg(P.z0w2 + (c + 2) * 64 + o) + hv.w * __ldg(P.z0w2 + (c + 3) * 64 + o);
        }
        __syncthreads();          // HR consumed; Y0Z (alias of HR) free after this
        s[HU_ + j * 64 + o] = a + b;
    }
    __syncthreads();
    if (tid < 128) {
        const int j = tid / 32, d = tid % 32;
        float mean = s[HU_ + j * 64 + d];
        float sd   = fabsf(s[HU_ + j * 64 + 32 + d]);
        float z = mean + __ldg(P.eps + (size_t)(row0 + j) * 32 + d) * sd;
        s[Y0Z_ + tid]   = z;
        s[KACCZ_ + tid] = 0.f;
        g_zs[(size_t)(row0 + j) * 32 + d] = z;   // t = 0
    }
    __syncthreads();

    // ---- stage decoder weights into the aliased W region ----
    {
        auto cp = [&](int off, const float* src, int n) {
            for (int i = tid; i < n; i += NT) s[off + i] = src[i];
        };
        cp(DW1_, P.dw1, 3200); cp(DB1_, P.db1, 100);
        cp(DW2_, P.dw2, 10000); cp(DB2_, P.db2, 100);
        cp(DW3_, P.dw3, 3200); cp(DB3_, P.db3, 32);
    }
    __syncthreads();

    // ================= DECODER: 199 RK4 steps, MLP 32->100->100->32 =================
    for (int it = 1; it < 200; it++) {
        const float dt = s[T_ + it] - s[T_ + it - 1];
        const float* curz = &s[Y0Z_];
        for (int e = 0; e < 4; e++) {
            if (tid < 200) {   // L1: 100 cols x 2 row-pairs
                const int c = tid % 100, r0 = (tid / 100) * 2;
                const float bb = s[DB1_ + c];
                float a0 = bb, b0 = 0.f, a1 = bb, b1 = 0.f;
                #pragma unroll
                for (int i4 = 0; i4 < 8; i4++) {
                    const int i = i4 * 4;
                    float4 v0 = *(const float4*)&curz[r0 * 32 + i];
                    float4 v1 = *(const float4*)&curz[(r0 + 1) * 32 + i];
                    float w0 = s[DW1_ + (i + 0) * 100 + c], w1v = s[DW1_ + (i + 1) * 100 + c];
                    float w2v = s[DW1_ + (i + 2) * 100 + c], w3v = s[DW1_ + (i + 3) * 100 + c];
                    a0 += v0.x * w0 + v0.y * w1v;  b0 += v0.z * w2v + v0.w * w3v;
                    a1 += v1.x * w0 + v1.y * w1v;  b1 += v1.z * w2v + v1.w * w3v;
                }
                s[HD1_ + r0 * 100 + c]       = ftanh(a0 + b0);
                s[HD1_ + (r0 + 1) * 100 + c] = ftanh(a1 + b1);
            }
            __syncthreads();
            if (tid < 200) {   // L2: 100x100, 2 row-pairs
                const int o = tid % 100, r0 = (tid / 100) * 2;
                const float bb = s[DB2_ + o];
                float a0 = bb, b0 = 0.f, a1 = bb, b1 = 0.f;
                #pragma unroll 5
                for (int c4 = 0; c4 < 25; c4++) {
                    const int c = c4 * 4;
                    float4 h0 = *(const float4*)&s[HD1_ + r0 * 100 + c];
                    float4 h1 = *(const float4*)&s[HD1_ + (r0 + 1) * 100 + c];
                    float w0 = s[DW2_ + (c + 0) * 100 + o], w1v = s[DW2_ + (c + 1) * 100 + o];
                    float w2v = s[DW2_ + (c + 2) * 100 + o], w3v = s[DW2_ + (c + 3) * 100 + o];
                    a0 += h0.x * w0 + h0.y * w1v;  b0 += h0.z * w2v + h0.w * w3v;
                    a1 += h1.x * w0 + h1.y * w1v;  b1 += h1.z * w2v + h1.w * w3v;
                }
                s[HD2_ + r0 * 100 + o]       = ftanh(a0 + b0);
                s[HD2_ + (r0 + 1) * 100 + o] = ftanh(a1 + b1);
            }
            __syncthreads();
            if (tid < 128) {   // L3 (100->32) full dot + RK4 update
                const int j = tid / 32, o = tid % 32;
                float a = s[DB3_ + o], b = 0.f;
                #pragma unroll 5
                for (int c4 = 0; c4 < 25; c4++) {
                    const int c = c4 * 4;
                    float4 hv = *(const float4*)&s[HD2_ + j * 100 + c];
                    a += hv.x * s[DW3_ + (c + 0) * 32 + o] + hv.y * s[DW3_ + (c + 1) * 32 + o];
                    b += hv.z * s[DW3_ + (c + 2) * 32 + o] + hv.w * s[DW3_ + (c + 3) * 32 + o];
                }
                float acc = a + b;
                if (e < 3) {
                    s[KACCZ_ + tid] += kw[e] * acc;
                    s[YSTZ_ + tid]   = s[Y0Z_ + tid] + sa[e] * dt * acc;
                } else {
                    float z = s[Y0Z_ + tid] + dt * (1.f / 6.f) * (s[KACCZ_ + tid] + acc);
                    s[Y0Z_ + tid]   = z;
                    s[KACCZ_ + tid] = 0.f;
                    g_zs[((size_t)it * 1024 + row0 + j) * 32 + o] = z;
                }
            }
            __syncthreads();
            curz = &s[YSTZ_];
        }
    }
}

// ===== epilogue: out[b,t,:] = z[t,b,:] @ ow + ob =====
__global__ void __launch_bounds__(256)
outproj_kernel(const float* __restrict__ ow, const float* __restrict__ ob,
               float* __restrict__ out)
{
    __shared__ float sw[4096];
    __shared__ float sb[128];
    __shared__ float sz[2048];   // 64 rows x 32
    const int tid = threadIdx.x;
    for (int i = tid; i < 4096; i += 256) sw[i] = ow[i];
    if (tid < 128) sb[tid] = ob[tid];
    const size_t r0 = (size_t)blockIdx.x * 64;
    for (int i = tid; i < 2048; i += 256) sz[i] = g_zs[r0 * 32 + i];
    __syncthreads();
    for (int ii = tid; ii < 8192; ii += 256) {
        const int q = ii >> 7, d = ii & 127;
        float a = sb[d], b = 0.f;
        #pragma unroll
        for (int i4 = 0; i4 < 8; i4++) {
            const int i = i4 * 4;
            float4 v = *(const float4*)&sz[q * 32 + i];
            a += v.x * sw[(i + 0) * 128 + d] + v.y * sw[(i + 1) * 128 + d];
            b += v.z * sw[(i + 2) * 128 + d] + v.w * sw[(i + 3) * 128 + d];
        }
        const size_t r = r0 + q;
        const int t = (int)(r / 1024), bb = (int)(r % 1024);
        out[((size_t)bb * 200 + t) * 128 + d] = a + b;
    }
}

extern "C" void kernel_launch(void* const* d_in, const int* in_sizes, int n_in,
                              void* d_out, int out_size)
{
    Params P;
    P.truth  = (const float*)d_in[0];  P.t     = (const float*)d_in[1];
    P.obs    = (const int*)  d_in[2];  P.eps   = (const float*)d_in[3];
    P.enc_w1 = (const float*)d_in[4];  P.enc_b1= (const float*)d_in[5];
    P.enc_w2 = (const float*)d_in[6];  P.enc_b2= (const float*)d_in[7];
    P.uw1 = (const float*)d_in[8];  P.ub1 = (const float*)d_in[9];
    P.uw2 = (const float*)d_in[10]; P.ub2 = (const float*)d_in[11];
    P.rw1 = (const float*)d_in[12]; P.rb1 = (const float*)d_in[13];
    P.rw2 = (const float*)d_in[14]; P.rb2 = (const float*)d_in[15];
    P.nw1 = (const float*)d_in[16]; P.nb1 = (const float*)d_in[17];
    P.nw2 = (const float*)d_in[18]; P.nb2 = (const float*)d_in[19];
    P.z0w1= (const float*)d_in[20]; P.z0b1= (const float*)d_in[21];
    P.z0w2= (const float*)d_in[22]; P.z0b2= (const float*)d_in[23];
    P.dw1 = (const float*)d_in[24]; P.db1 = (const float*)d_in[25];
    P.dw2 = (const float*)d_in[26]; P.db2 = (const float*)d_in[27];
    P.dw3 = (const float*)d_in[28]; P.db3 = (const float*)d_in[29];
    P.ow  = (const float*)d_in[30]; P.ob  = (const float*)d_in[31];

    transpose_w1_kernel<<<(3 * 42 * 200 + 255) / 256, 256>>>(P.uw1, P.rw1, P.nw1);

    const size_t smem = SMEM_FLOATS * sizeof(float);   // 90,608 B -> 2 blocks/SM
    cudaFuncSetAttribute(lode_kernel,
                         cudaFuncAttributeMaxDynamicSharedMemorySize, (int)smem);
    lode_kernel<<<256, NT, smem>>>(P, (float*)d_out);

    outproj_kernel<<<3200, 256>>>(P.ow, P.ob, (float*)d_out);
}